// round 7
// baseline (speedup 1.0000x reference)
#include <cuda_runtime.h>

#define BATCH   64
#define TPB     512                 // 16 warps
#define NBLK    (BATCH * 2)        // 2 CTAs per image
#define NPATCH  (127 * 127)

// per-CTA partials: [0]=(T,TC,m2,m3) [1]=(CC0,C0,CC127,C127)
//                   [2]=(Rtop,Rbot,cTL,cTR) [3]=(cBL,cBR,-,-)
__device__ float4       g_part[NBLK][4];
__device__ unsigned int g_cnt[BATCH];   // zero-init; finisher resets

__global__ void __launch_bounds__(TPB, 1) fused_kernel(
    const float* __restrict__ x,
    const float* __restrict__ conv_w,
    const float* __restrict__ conv_b,
    const float* __restrict__ ry,
    const float* __restrict__ head_w,
    const float* __restrict__ head_b,
    float* __restrict__ out)
{
    __shared__ float sh[16][10];
    __shared__ float tot[8];
    __shared__ float sc[4];      // cTL, cTR, cBL, cBR

    const int tid  = threadIdx.x;
    const int wid  = tid >> 5;
    const int lane = tid & 31;
    const int b    = blockIdx.x >> 1;   // image
    const int q    = blockIdx.x & 1;    // half (64 rows)
    const bool ctrl = (tid == 480);     // warp15 lane0

    // Controller prefetches params (used only in overlap phase).
    float pr[8], pwt[4], pcb, ph0, ph1, phb;
    if (ctrl) {
        #pragma unroll
        for (int i = 0; i < 8; i++) pr[i] = ry[i];
        #pragma unroll
        for (int i = 0; i < 4; i++) pwt[i] = conv_w[i];
        pcb = conv_b[0]; ph0 = head_w[0]; ph1 = head_w[1]; phb = head_b[0];
    }

    // ---- front-batched loads: warp owns 4 rows, lane owns 4 cols ----
    const int rowbase = q * 64 + wid * 4;
    const float* __restrict__ p = x + (size_t)b * 16384 + rowbase * 128 + lane * 4;
    float4 v[4];
    #pragma unroll
    for (int i = 0; i < 4; i++) v[i] = *(const float4*)(p + i * 128);

    float A_T = 0.f, A_TC = 0.f, A_m2 = 0.f, A_m3 = 0.f;
    float A_CC0 = 0.f, A_CC127 = 0.f;
    float rsF = 0.f, rsL = 0.f;

    const bool l31 = (lane == 31);

    #pragma unroll
    for (int i = 0; i < 4; i++) {
        const int   row = rowbase + i;      // warp-uniform
        const float4 vv = v[i];

        const float rs = (vv.x + vv.y) + (vv.z + vv.w);
        A_T += rs;
        if (i == 0) rsF = rs;
        if (i == 3) rsL = rs;

        if (row < 127) {   // trig rows only
            float ca0, sa0, ca1, sa1, ca2, sa2, ca3, sa3;
            __sincosf(vv.x, &sa0, &ca0);
            __sincosf(vv.y, &sa1, &ca1);
            __sincosf(vv.z, &sa2, &ca2);
            __sincosf(vv.w, &sa3, &ca3);
            float ca4 = __shfl_down_sync(0xFFFFFFFFu, ca0, 1);
            float sa4 = __shfl_down_sync(0xFFFFFFFFu, sa0, 1);
            if (l31) { ca4 = 0.f; sa4 = 0.f; }

            A_TC    += (ca0 + ca1) + (ca2 + ca3);
            A_CC0   += ca0;   // lane0's value used
            A_CC127 += ca3;   // lane31's value used
            A_m2    += ca0 * ca1 + ca1 * ca2 + ca2 * ca3 + ca3 * ca4;
            A_m3    += sa0 * sa1 + sa1 * sa2 + sa2 * sa3 + sa3 * sa4;
        }
    }

    // full-column sums from registers (lane0 / lane31 values used)
    const float A_C0   = (v[0].x + v[1].x) + (v[2].x + v[3].x);
    const float A_C127 = (v[0].w + v[1].w) + (v[2].w + v[3].w);

    // corners (before barrier)
    if (wid == 0  && lane == 0)  sc[0] = v[0].x;   // cTL  (row rowbase, col 0)
    if (wid == 0  && lane == 31) sc[1] = v[0].w;   // cTR  (col 127)
    if (wid == 15 && lane == 0)  sc[2] = v[3].x;   // cBL  (row rowbase+3)
    if (wid == 15 && lane == 31) sc[3] = v[3].w;   // cBR

    // ---- warp tree reduction: 6 chains ----
    #pragma unroll
    for (int off = 16; off > 0; off >>= 1) {
        const unsigned m = 0xFFFFFFFFu;
        A_T  += __shfl_down_sync(m, A_T,  off);
        A_TC += __shfl_down_sync(m, A_TC, off);
        A_m2 += __shfl_down_sync(m, A_m2, off);
        A_m3 += __shfl_down_sync(m, A_m3, off);
        rsF  += __shfl_down_sync(m, rsF,  off);
        rsL  += __shfl_down_sync(m, rsL,  off);
    }
    if (lane == 0) {
        sh[wid][0] = A_T;  sh[wid][1] = A_TC;
        sh[wid][2] = A_m2; sh[wid][3] = A_m3;
        sh[wid][4] = rsF;  sh[wid][5] = rsL;
        sh[wid][6] = A_CC0;            // lane0 scalar
        sh[wid][7] = A_C0;
    }
    if (lane == 31) {
        sh[wid][8] = A_CC127;          // lane31 scalar
        sh[wid][9] = A_C127;
    }
    __syncthreads();

    // ---- cross-warp: warps 0-7 each sum one column over 16 warps ----
    if (wid < 8) {
        const int colmap[8] = {0, 1, 2, 3, 6, 7, 8, 9};
        const int col = colmap[wid];
        float vv = (lane < 16) ? sh[lane][col] : 0.f;
        vv += __shfl_down_sync(0xFFFFFFFFu, vv, 8);
        vv += __shfl_down_sync(0xFFFFFFFFu, vv, 4);
        vv += __shfl_down_sync(0xFFFFFFFFu, vv, 2);
        vv += __shfl_down_sync(0xFFFFFFFFu, vv, 1);
        if (lane == 0) tot[wid] = vv;
    }

    // ---- controller overlaps coefficient math with the reduce above ----
    float Ac = 0.f, Bc = 0.f, Cc = 0.f, Dc = 0.f, Ec = 0.f;
    float cw0 = 0.f, cw1 = 0.f, cw2 = 0.f, cw3 = 0.f, cK = 0.f;
    if (ctrl) {
        float U[4][4] = {{1,0,0,0},{0,1,0,0},{0,0,1,0},{0,0,0,1}};
        #pragma unroll
        for (int l = 0; l < 2; l++) {
            float c0, s0, c1, s1;
            __sincosf(0.5f * pr[l * 4 + 0], &s0, &c0);
            __sincosf(0.5f * pr[l * 4 + 1], &s1, &c1);
            float A2[2][2] = {{c0, -s0}, {s0, c0}};
            float B2[2][2] = {{c1, -s1}, {s1, c1}};
            float T4[4][4];
            #pragma unroll
            for (int i = 0; i < 4; i++)
                #pragma unroll
                for (int j = 0; j < 4; j++) {
                    float s = 0.f;
                    #pragma unroll
                    for (int kx = 0; kx < 4; kx++)
                        s += A2[i >> 1][kx >> 1] * B2[i & 1][kx & 1] * U[kx][j];
                    T4[i][j] = s;
                }
            #pragma unroll
            for (int j = 0; j < 4; j++) {
                U[0][j] = T4[0][j]; U[1][j] = T4[1][j];
                U[2][j] = T4[3][j]; U[3][j] = T4[2][j];
            }
        }
        float M00 = 0, M03 = 0, M33 = 0, M11 = 0, M12 = 0, M22 = 0;
        #pragma unroll
        for (int i = 0; i < 4; i++) {
            float z = (i < 2) ? 1.0f : -1.0f;
            M00 += z * U[i][0] * U[i][0];
            M03 += z * U[i][0] * U[i][3];
            M33 += z * U[i][3] * U[i][3];
            M11 += z * U[i][1] * U[i][1];
            M12 += z * U[i][1] * U[i][2];
            M22 += z * U[i][2] * U[i][2];
        }
        const float c_q0 = ph1 * M00;
        const float c_q1 = ph1 * (-2.0f * M03);
        const float c_q2 = ph1 * M33;
        const float c_q3 = ph1 * M11;
        const float c_q4 = ph1 * (2.0f * M12);
        const float c_q5 = ph1 * M22;
        Ac = 0.25f * (c_q0 + c_q2 + c_q3 + c_q5);
        Bc = 0.25f * (c_q0 - c_q2 + c_q3 - c_q5);
        Cc = 0.25f * (c_q0 - c_q2 - c_q3 + c_q5);
        Dc = 0.25f * (c_q0 + c_q2 - c_q3 - c_q5);
        Ec = 0.25f * (c_q1 + c_q4);
        cw0 = ph0 * pwt[0]; cw1 = ph0 * pwt[1];
        cw2 = ph0 * pwt[2]; cw3 = ph0 * pwt[3];
        cK  = ph0 * pcb + phb;
    }
    __syncthreads();

    if (ctrl) {
        const float4 p0 = make_float4(tot[0], tot[1], tot[2], tot[3]);
        const float4 p1 = make_float4(tot[4], tot[5], tot[6], tot[7]);
        const float4 p2 = make_float4(sh[0][4], sh[15][5], sc[0], sc[1]);
        const float4 p3 = make_float4(sc[2], sc[3], 0.f, 0.f);
        g_part[blockIdx.x][0] = p0;
        g_part[blockIdx.x][1] = p1;
        g_part[blockIdx.x][2] = p2;
        g_part[blockIdx.x][3] = p3;
        __threadfence();
        const unsigned done = atomicAdd(&g_cnt[b], 1u);
        if (done == 1u) {
            __threadfence();
            const int prt = blockIdx.x ^ 1;
            const float4 r0 = __ldcg(&g_part[prt][0]);
            const float4 r1 = __ldcg(&g_part[prt][1]);
            const float4 r2 = __ldcg(&g_part[prt][2]);
            const float4 r3 = __ldcg(&g_part[prt][3]);
            // fixed order: even CTA first
            const float4 e0 = q ? r0 : p0, o0 = q ? p0 : r0;
            const float4 e1 = q ? r1 : p1, o1 = q ? p1 : r1;
            const float4 e2 = q ? r2 : p2, o2 = q ? p2 : r2;
            const float4 e3 = q ? r3 : p3, o3 = q ? p3 : r3;

            const float T   = e0.x + o0.x;
            const float TC  = e0.y + o0.y;
            const float m2  = e0.z + o0.z;
            const float m3  = e0.w + o0.w;
            const float CC0 = e1.x + o1.x;
            const float C0  = e1.y + o1.y;
            const float CC127 = e1.z + o1.z;
            const float C127  = e1.w + o1.w;
            const float R0   = e2.x;     // even CTA's top row (row 0)
            const float R127 = o2.y;     // odd CTA's bottom row (row 127)
            const float x00     = e2.z;
            const float x0_127  = e2.w;
            const float x127_0  = o3.x;
            const float x127_127 = o3.y;

            const float m0 = TC - CC127;
            const float m1 = TC - CC0;
            const float m4 = T - C127 - R127 + x127_127;
            const float m5 = T - C0   - R127 + x127_0;
            const float m6 = T - C127 - R0   + x0_127;
            const float m7 = T - C0   - R0   + x00;

            const float qsum = Ac * (float)NPATCH + Bc * m0 + Cc * m1
                             + Dc * m2 + Ec * m3;
            const float csum = cw0 * m4 + cw1 * m5 + cw2 * m6 + cw3 * m7;
            out[b] = (qsum + csum) * (1.0f / (float)NPATCH) + cK;

            g_cnt[b] = 0;   // reset for next graph replay
        }
    }
}

extern "C" void kernel_launch(void* const* d_in, const int* in_sizes, int n_in,
                              void* d_out, int out_size) {
    const float* x      = (const float*)d_in[0];
    const float* conv_w = (const float*)d_in[1];
    const float* conv_b = (const float*)d_in[2];
    const float* ry     = (const float*)d_in[3];
    const float* head_w = (const float*)d_in[4];
    const float* head_b = (const float*)d_in[5];
    float* out = (float*)d_out;

    fused_kernel<<<NBLK, TPB>>>(x, conv_w, conv_b, ry, head_w, head_b, out);
}

// round 8
// speedup vs baseline: 1.3478x; 1.3478x over previous
#include <cuda_runtime.h>
#include <cstdint>

#define BATCH   64
#define NBLK    (BATCH * 2)     // 2-CTA cluster per image
#define TPB     544             // 17 warps: 16 compute + 1 controller
#define NPATCH  (127 * 127)

__device__ __forceinline__ uint32_t smem_u32(const void* p) {
    uint32_t a;
    asm("{ .reg .u64 t; cvta.to.shared.u64 t, %1; cvt.u32.u64 %0, t; }"
        : "=r"(a) : "l"(p));
    return a;
}

__global__ void __launch_bounds__(TPB, 1) __cluster_dims__(2, 1, 1)
fused_kernel(
    const float* __restrict__ x,
    const float* __restrict__ conv_w,
    const float* __restrict__ conv_b,
    const float* __restrict__ ry,      // (2,4)
    const float* __restrict__ head_w,  // (1,2)
    const float* __restrict__ head_b,
    float* __restrict__ out)
{
    __shared__ float sh[16][9];     // [compute-warp][monomial], padded
    __shared__ float tot[8];        // this CTA's 8 monomial sums
    __shared__ float peer[8];       // CTA0: filled remotely by CTA1
    __shared__ __align__(8) unsigned long long mbar;

    const int tid  = threadIdx.x;
    const int wid  = tid >> 5;
    const int lane = tid & 31;
    const int b    = blockIdx.x >> 1;
    uint32_t rank;
    asm("mov.u32 %0, %%cluster_ctarank;" : "=r"(rank));

    const uint32_t mbar_a = smem_u32(&mbar);
    const uint32_t peer_a = smem_u32(peer);

    // mbarrier init (CTA0 only), ordered before any remote arrive by the
    // split cluster barrier below.
    if (rank == 0 && tid == 0) {
        asm volatile("mbarrier.init.shared.b64 [%0], 1;" :: "r"(mbar_a) : "memory");
    }
    __syncthreads();
    asm volatile("barrier.cluster.arrive.aligned;" ::: "memory");

    // ---- front-batched pixel loads (compute warps) ----
    const int rowbase = (int)rank * 64 + wid * 4;
    float4 v[4];
    if (wid < 16) {
        const float* __restrict__ p =
            x + (size_t)b * 16384 + rowbase * 128 + lane * 4;
        #pragma unroll
        for (int i = 0; i < 4; i++) v[i] = *(const float4*)(p + i * 128);
    }

    // ---- controller (warp 16, lane 0, rank 0): coefficient math,
    //      fully overlapped with the DRAM load wall + main phase ----
    float Ac = 0.f, Bc = 0.f, Cc = 0.f, Dc = 0.f, Ec = 0.f;
    float cw0 = 0.f, cw1 = 0.f, cw2 = 0.f, cw3 = 0.f, cK = 0.f;
    if (rank == 0 && wid == 16 && lane == 0) {
        float pr[8];
        #pragma unroll
        for (int i = 0; i < 8; i++) pr[i] = ry[i];
        const float ph0 = head_w[0], ph1 = head_w[1];

        float U[4][4] = {{1,0,0,0},{0,1,0,0},{0,0,1,0},{0,0,0,1}};
        #pragma unroll
        for (int l = 0; l < 2; l++) {
            float c0, s0, c1, s1;
            __sincosf(0.5f * pr[l * 4 + 0], &s0, &c0);
            __sincosf(0.5f * pr[l * 4 + 1], &s1, &c1);
            float A2[2][2] = {{c0, -s0}, {s0, c0}};
            float B2[2][2] = {{c1, -s1}, {s1, c1}};
            float T4[4][4];
            #pragma unroll
            for (int i = 0; i < 4; i++)
                #pragma unroll
                for (int j = 0; j < 4; j++) {
                    float s = 0.f;
                    #pragma unroll
                    for (int kx = 0; kx < 4; kx++)
                        s += A2[i >> 1][kx >> 1] * B2[i & 1][kx & 1] * U[kx][j];
                    T4[i][j] = s;
                }
            #pragma unroll
            for (int j = 0; j < 4; j++) {
                U[0][j] = T4[0][j]; U[1][j] = T4[1][j];
                U[2][j] = T4[3][j]; U[3][j] = T4[2][j];
            }
        }
        float M00 = 0, M03 = 0, M33 = 0, M11 = 0, M12 = 0, M22 = 0;
        #pragma unroll
        for (int i = 0; i < 4; i++) {
            float z = (i < 2) ? 1.0f : -1.0f;
            M00 += z * U[i][0] * U[i][0];
            M03 += z * U[i][0] * U[i][3];
            M33 += z * U[i][3] * U[i][3];
            M11 += z * U[i][1] * U[i][1];
            M12 += z * U[i][1] * U[i][2];
            M22 += z * U[i][2] * U[i][2];
        }
        const float c_q0 = ph1 * M00;
        const float c_q1 = ph1 * (-2.0f * M03);
        const float c_q2 = ph1 * M33;
        const float c_q3 = ph1 * M11;
        const float c_q4 = ph1 * (2.0f * M12);
        const float c_q5 = ph1 * M22;
        Ac = 0.25f * (c_q0 + c_q2 + c_q3 + c_q5);
        Bc = 0.25f * (c_q0 - c_q2 + c_q3 - c_q5);
        Cc = 0.25f * (c_q0 - c_q2 - c_q3 + c_q5);
        Dc = 0.25f * (c_q0 + c_q2 - c_q3 - c_q5);
        Ec = 0.25f * (c_q1 + c_q4);
        cw0 = ph0 * conv_w[0]; cw1 = ph0 * conv_w[1];
        cw2 = ph0 * conv_w[2]; cw3 = ph0 * conv_w[3];
        cK  = ph0 * conv_b[0] + head_b[0];
    }

    // Complete the cluster barrier (hides under the load wall).
    asm volatile("barrier.cluster.wait.aligned;" ::: "memory");

    // ---- main phase (compute warps) ----
    float S0 = 0.f, S1 = 0.f, S2 = 0.f, S3 = 0.f;
    float S4 = 0.f, S5 = 0.f, S6 = 0.f, S7 = 0.f;
    if (wid < 16) {
        const bool l31 = (lane == 31);
        const bool l0  = (lane == 0);
        #pragma unroll
        for (int i = 0; i < 4; i++) {
            const int   row = rowbase + i;     // warp-uniform
            const float4 vv = v[i];
            const float rs = (vv.x + vv.y) + (vv.z + vv.w);
            const float e0 = l0  ? vv.x : 0.f;
            const float e3 = l31 ? vv.w : 0.f;

            if (row < 127) {
                S4 += rs - e3;                 // La0
                S5 += rs - e0;                 // La1
                float ca0, sa0, ca1, sa1, ca2, sa2, ca3, sa3;
                __sincosf(vv.x, &sa0, &ca0);
                __sincosf(vv.y, &sa1, &ca1);
                __sincosf(vv.z, &sa2, &ca2);
                __sincosf(vv.w, &sa3, &ca3);
                const float ca4 = __shfl_down_sync(0xFFFFFFFFu, ca0, 1);
                const float sa4 = __shfl_down_sync(0xFFFFFFFFu, sa0, 1);
                const float tc = (ca0 + ca1) + (ca2 + ca3);
                S0 += tc - (l31 ? ca3 : 0.f);  // Sca0
                S1 += tc - (l0  ? ca0 : 0.f);  // Sca1
                S2 += ca0 * ca1 + ca1 * ca2 + ca2 * ca3 + (l31 ? 0.f : ca3 * ca4);
                S3 += sa0 * sa1 + sa1 * sa2 + sa2 * sa3 + (l31 ? 0.f : sa3 * sa4);
            }
            if (row > 0) {
                S6 += rs - e3;                 // La2
                S7 += rs - e0;                 // La3
            }
        }

        // warp tree reduction (deterministic)
        #pragma unroll
        for (int off = 16; off > 0; off >>= 1) {
            const unsigned m = 0xFFFFFFFFu;
            S0 += __shfl_down_sync(m, S0, off);
            S1 += __shfl_down_sync(m, S1, off);
            S2 += __shfl_down_sync(m, S2, off);
            S3 += __shfl_down_sync(m, S3, off);
            S4 += __shfl_down_sync(m, S4, off);
            S5 += __shfl_down_sync(m, S5, off);
            S6 += __shfl_down_sync(m, S6, off);
            S7 += __shfl_down_sync(m, S7, off);
        }
        if (lane == 0) {
            sh[wid][0] = S0; sh[wid][1] = S1; sh[wid][2] = S2; sh[wid][3] = S3;
            sh[wid][4] = S4; sh[wid][5] = S5; sh[wid][6] = S6; sh[wid][7] = S7;
        }
    }
    __syncthreads();

    // cross-warp: warps 0-7 each reduce one monomial over 16 warps
    if (wid < 8) {
        float vv = (lane < 16) ? sh[lane][wid] : 0.f;
        vv += __shfl_down_sync(0xFFFFFFFFu, vv, 8);
        vv += __shfl_down_sync(0xFFFFFFFFu, vv, 4);
        vv += __shfl_down_sync(0xFFFFFFFFu, vv, 2);
        vv += __shfl_down_sync(0xFFFFFFFFu, vv, 1);
        if (lane == 0) tot[wid] = vv;
    }
    __syncthreads();

    // ---- CTA1: ship 8 sums to CTA0 via DSMEM, then release-arrive ----
    if (rank == 1 && wid == 16 && lane == 0) {
        uint32_t rp, rm;
        asm("mapa.shared::cluster.u32 %0, %1, 0;" : "=r"(rp) : "r"(peer_a));
        asm("mapa.shared::cluster.u32 %0, %1, 0;" : "=r"(rm) : "r"(mbar_a));
        #pragma unroll
        for (int i = 0; i < 8; i++) {
            asm volatile("st.shared::cluster.f32 [%0], %1;"
                         :: "r"(rp + 4 * i), "f"(tot[i]) : "memory");
        }
        asm volatile(
            "mbarrier.arrive.release.cluster.shared::cluster.b64 _, [%0];"
            :: "r"(rm) : "memory");
    }

    // ---- CTA0 controller: wait, combine, store ----
    if (rank == 0 && wid == 16 && lane == 0) {
        asm volatile(
            "{\n\t"
            ".reg .pred p;\n\t"
            "W%=:\n\t"
            "mbarrier.try_wait.parity.acquire.cluster.shared::cta.b64 p, [%0], 0, 0x989680;\n\t"
            "@p bra D%=;\n\t"
            "bra W%=;\n\t"
            "D%=:\n\t"
            "}"
            :: "r"(mbar_a) : "memory");

        // fixed order: CTA0 (rows 0-63) + CTA1 (rows 64-127)
        const float m0 = tot[0] + peer[0];
        const float m1 = tot[1] + peer[1];
        const float m2 = tot[2] + peer[2];
        const float m3 = tot[3] + peer[3];
        const float m4 = tot[4] + peer[4];
        const float m5 = tot[5] + peer[5];
        const float m6 = tot[6] + peer[6];
        const float m7 = tot[7] + peer[7];

        const float qsum = Ac * (float)NPATCH + Bc * m0 + Cc * m1
                         + Dc * m2 + Ec * m3;
        const float csum = cw0 * m4 + cw1 * m5 + cw2 * m6 + cw3 * m7;
        out[b] = (qsum + csum) * (1.0f / (float)NPATCH) + cK;
    }
}

extern "C" void kernel_launch(void* const* d_in, const int* in_sizes, int n_in,
                              void* d_out, int out_size) {
    const float* x      = (const float*)d_in[0];
    const float* conv_w = (const float*)d_in[1];
    const float* conv_b = (const float*)d_in[2];
    const float* ry     = (const float*)d_in[3];
    const float* head_w = (const float*)d_in[4];
    const float* head_b = (const float*)d_in[5];
    float* out = (float*)d_out;

    fused_kernel<<<NBLK, TPB>>>(x, conv_w, conv_b, ry, head_w, head_b, out);
}